// round 8
// baseline (speedup 1.0000x reference)
#include <cuda_runtime.h>
#include <cstdint>

#define B_WIN   4096
#define NTOK    49
#define DIMC    384
#define NH      12
#define HD      32
#define M_TOTAL (B_WIN * NTOK)     // 200704
#define KDIM    384
#define QK_SCALE 0.17677669529663687f

// ---------------- scratch (no cudaMalloc allowed) ----------------
__device__ float g_qkv[(size_t)M_TOTAL * 1152];   // ~925 MB
__device__ float g_att[(size_t)M_TOTAL * DIMC];   // ~308 MB (tf32-rounded by attn)
__device__ float g_xr[(size_t)M_TOTAL * KDIM];    // ~308 MB tf32-rounded x
__device__ float g_wqkv[1152 * KDIM];
__device__ float g_wproj[DIMC * KDIM];
__device__ float g_bias[NH * NTOK * NTOK];

// ---------------- helpers ----------------
__device__ __forceinline__ uint32_t f2tf(float f) {
    uint32_t r;
    asm("cvt.rna.tf32.f32 %0, %1;" : "=r"(r) : "f"(f));
    return r;
}
__device__ __forceinline__ void cpa16(float* smem, const float* g) {
    uint32_t s = (uint32_t)__cvta_generic_to_shared(smem);
    asm volatile("cp.async.cg.shared.global [%0], [%1], 16;\n" :: "r"(s), "l"(g));
}
__device__ __forceinline__ uint64_t fma2(uint64_t a, uint64_t b, uint64_t c) {
    uint64_t d;
    asm("fma.rn.f32x2 %0, %1, %2, %3;" : "=l"(d) : "l"(a), "l"(b), "l"(c));
    return d;
}
__device__ __forceinline__ uint64_t add2(uint64_t a, uint64_t b) {
    uint64_t d;
    asm("add.rn.f32x2 %0, %1, %2;" : "=l"(d) : "l"(a), "l"(b));
    return d;
}

// ---------------- pre-pass: round to tf32 (RNA) ----------------
__global__ void round_tf32_kernel(const float* __restrict__ src, int n4, int mode) {
    float* dst = (mode == 0) ? g_xr : (mode == 1) ? g_wqkv : g_wproj;
    int i = blockIdx.x * blockDim.x + threadIdx.x;
    if (i < n4) {
        float4 v = ((const float4*)src)[i];
        float4 o;
        o.x = __uint_as_float(f2tf(v.x));
        o.y = __uint_as_float(f2tf(v.y));
        o.z = __uint_as_float(f2tf(v.z));
        o.w = __uint_as_float(f2tf(v.w));
        ((float4*)dst)[i] = o;
    }
}

__global__ void bias_expand_kernel(const float* __restrict__ bt, const int* __restrict__ ri) {
    int h = blockIdx.x;
    for (int e = threadIdx.x; e < NTOK * NTOK; e += blockDim.x)
        g_bias[h * NTOK * NTOK + e] = bt[ri[e] * NH + h];
}

// ---------------- tf32 mma.sync GEMM: C[M,Nc] = A[M,K] @ W[Nc,K]^T + bias ----------------
// BM=128, BN=128, BK=32, 256 threads = 8 warps (4 in M x 2 in N), warp tile 32x64.
// 1.5 LDS per MMA (vs 2.0 in R5) at the SAME 8-warp latency hiding.
#define BM  128
#define BN  128
#define BK  32
#define SMEM_DYN (2 * (BM * BK + BN * BK) * 4)   // 64 KB

__device__ __forceinline__ int sw_store(int row, int c4) {
    return row * 32 + ((c4 ^ (row & 7)) << 2);
}
__device__ __forceinline__ uint32_t sw_loadu(const uint32_t* buf, int row, int kc) {
    return buf[row * 32 + ((((kc >> 2)) ^ (row & 7)) << 2) + (kc & 3)];
}

__global__ __launch_bounds__(256, 2) void gemm_tf32_kernel(
    const float* __restrict__ bias, float* __restrict__ Cext, int Nc, int mode)
{
    const float* A = (mode == 0) ? g_xr : g_att;
    const float* W = (mode == 0) ? g_wqkv : g_wproj;
    float*       C = (mode == 0) ? g_qkv : Cext;

    extern __shared__ float dyn_s[];
    float* As[2] = { dyn_s,               dyn_s + BM * BK };
    float* Bs[2] = { dyn_s + 2 * BM * BK, dyn_s + 2 * BM * BK + BN * BK };

    const int tid    = threadIdx.x;
    const int warp   = tid >> 5;
    const int lane   = tid & 31;
    const int g      = lane >> 2;
    const int tg     = lane & 3;
    const int warp_m = warp >> 1;      // 0..3
    const int warp_n = warp & 1;       // 0..1

    const size_t mbase = (size_t)blockIdx.y * BM;
    const size_t nbase = (size_t)blockIdx.x * BN;
    const int KT = KDIM / BK;          // 12

    const int lrow = tid >> 3;         // 0..31
    const int lc4  = tid & 7;

    float acc[2][8][4];
#pragma unroll
    for (int ma = 0; ma < 2; ma++)
#pragma unroll
        for (int na = 0; na < 8; na++)
#pragma unroll
            for (int i = 0; i < 4; i++) acc[ma][na][i] = 0.f;

    auto issue = [&](int t, int buf) {
        const float* Ag = A + (mbase + lrow) * KDIM + t * BK + lc4 * 4;
#pragma unroll
        for (int i = 0; i < 4; i++)
            cpa16(&As[buf][sw_store(lrow + i * 32, lc4)], Ag + (size_t)i * 32 * KDIM);
        const float* Wg = W + (nbase + lrow) * KDIM + t * BK + lc4 * 4;
#pragma unroll
        for (int i = 0; i < 4; i++)
            cpa16(&Bs[buf][sw_store(lrow + i * 32, lc4)], Wg + (size_t)i * 32 * KDIM);
        asm volatile("cp.async.commit_group;\n");
    };

    auto compute = [&](int cur) {
        const uint32_t* Ab = (const uint32_t*)As[cur];
        const uint32_t* Bb = (const uint32_t*)Bs[cur];
#pragma unroll
        for (int ks = 0; ks < 4; ks++) {
            const int kc = ks * 8 + tg;
            uint32_t a[2][4];
#pragma unroll
            for (int ma = 0; ma < 2; ma++) {
                const int r = warp_m * 32 + ma * 16 + g;
                a[ma][0] = sw_loadu(Ab, r,     kc);
                a[ma][1] = sw_loadu(Ab, r + 8, kc);
                a[ma][2] = sw_loadu(Ab, r,     kc + 4);
                a[ma][3] = sw_loadu(Ab, r + 8, kc + 4);
            }
#pragma unroll
            for (int na = 0; na < 8; na++) {
                const int rb = warp_n * 64 + na * 8 + g;
                uint32_t b0 = sw_loadu(Bb, rb, kc);
                uint32_t b1 = sw_loadu(Bb, rb, kc + 4);
#pragma unroll
                for (int ma = 0; ma < 2; ma++) {
                    asm volatile(
                        "mma.sync.aligned.m16n8k8.row.col.f32.tf32.tf32.f32 "
                        "{%0,%1,%2,%3}, {%4,%5,%6,%7}, {%8,%9}, {%0,%1,%2,%3};\n"
                        : "+f"(acc[ma][na][0]), "+f"(acc[ma][na][1]),
                          "+f"(acc[ma][na][2]), "+f"(acc[ma][na][3])
                        : "r"(a[ma][0]), "r"(a[ma][1]), "r"(a[ma][2]), "r"(a[ma][3]),
                          "r"(b0), "r"(b1));
                }
            }
        }
    };

    issue(0, 0);
#pragma unroll 1
    for (int t = 0; t < KT; t++) {
        asm volatile("cp.async.wait_group 0;\n" ::: "memory");
        __syncthreads();
        if (t + 1 < KT) issue(t + 1, (t + 1) & 1);
        compute(t & 1);
    }

    // epilogue
#pragma unroll
    for (int ma = 0; ma < 2; ma++) {
        const size_t r0 = mbase + warp_m * 32 + ma * 16 + g;
#pragma unroll
        for (int na = 0; na < 8; na++) {
            const size_t col = nbase + warp_n * 64 + na * 8 + tg * 2;
            float b0 = __ldg(&bias[col]), b1 = __ldg(&bias[col + 1]);
            *(float2*)&C[r0 * (size_t)Nc + col] =
                make_float2(acc[ma][na][0] + b0, acc[ma][na][1] + b1);
            *(float2*)&C[(r0 + 8) * (size_t)Nc + col] =
                make_float2(acc[ma][na][2] + b0, acc[ma][na][3] + b1);
        }
    }
}

// ---------------- per-(window, head) attention (f32x2 packed math) ----------------
__global__ __launch_bounds__(64) void attn_kernel()
{
    __shared__ __align__(16) float k_s[NTOK][HD];
    __shared__ __align__(16) float v_s[NTOK][HD];

    const int bid = blockIdx.x;
    const int b = bid / NH, h = bid % NH;
    const float* base = g_qkv + (size_t)b * NTOK * 1152;
    const int tid = threadIdx.x;

    // prefetch q packed as f32x2 pairs before the K/V barrier
    uint64_t q2[16];
    if (tid < NTOK) {
        const ulonglong2* qp = (const ulonglong2*)(base + (size_t)tid * 1152 + h * HD);
#pragma unroll
        for (int c = 0; c < 8; c++) {
            ulonglong2 t = qp[c];
            q2[2 * c] = t.x; q2[2 * c + 1] = t.y;
        }
    }

    for (int idx = tid; idx < NTOK * 8; idx += 64) {
        int j = idx >> 3, dd = idx & 7;
        const float4* kp = (const float4*)(base + (size_t)j * 1152 + 384 + h * HD);
        *((float4*)&k_s[j][dd * 4]) = kp[dd];
        const float4* vp = (const float4*)(base + (size_t)j * 1152 + 768 + h * HD);
        *((float4*)&v_s[j][dd * 4]) = vp[dd];
    }
    __syncthreads();

    if (tid < NTOK) {
        const float* gb = g_bias + h * (NTOK * NTOK) + tid * NTOK;
        float s[NTOK];
        float mx = -1e30f;
#pragma unroll
        for (int j = 0; j < NTOK; j++) {
            const ulonglong2* kr = (const ulonglong2*)k_s[j];
            uint64_t a0 = 0ull, a1 = 0ull, a2 = 0ull, a3 = 0ull;
#pragma unroll
            for (int c = 0; c < 4; c++) {
                ulonglong2 t0 = kr[c];
                ulonglong2 t1 = kr[c + 4];
                a0 = fma2(q2[2 * c],     t0.x, a0);
                a1 = fma2(q2[2 * c + 1], t0.y, a1);
                a2 = fma2(q2[2 * c + 8], t1.x, a2);
                a3 = fma2(q2[2 * c + 9], t1.y, a3);
            }
            a0 = add2(a0, a1);
            a2 = add2(a2, a3);
            a0 = add2(a0, a2);
            uint32_t lo, hi;
            asm("mov.b64 {%0, %1}, %2;" : "=r"(lo), "=r"(hi) : "l"(a0));
            float acc = __uint_as_float(lo) + __uint_as_float(hi);
            float val = acc * QK_SCALE + __ldg(&gb[j]);
            s[j] = val;
            mx = fmaxf(mx, val);
        }

        float sum = 0.f;
#pragma unroll
        for (int j = 0; j < NTOK; j++) {
            float e = __expf(s[j] - mx);
            s[j] = e;
            sum += e;
        }
        float inv = 1.f / sum;

        uint64_t o2[16];
#pragma unroll
        for (int i = 0; i < 16; i++) o2[i] = 0ull;
#pragma unroll
        for (int j = 0; j < NTOK; j++) {
            uint32_t pu = __float_as_uint(s[j]);
            uint64_t p2;
            asm("mov.b64 %0, {%1, %2};" : "=l"(p2) : "r"(pu), "r"(pu));
            const ulonglong2* vr = (const ulonglong2*)v_s[j];
#pragma unroll
            for (int c = 0; c < 8; c++) {
                ulonglong2 t = vr[c];
                o2[2 * c]     = fma2(p2, t.x, o2[2 * c]);
                o2[2 * c + 1] = fma2(p2, t.y, o2[2 * c + 1]);
            }
        }

        float* op = g_att + ((size_t)b * NTOK + tid) * DIMC + h * HD;
#pragma unroll
        for (int c = 0; c < 8; c++) {
            uint32_t l0, h0, l1, h1;
            asm("mov.b64 {%0, %1}, %2;" : "=r"(l0), "=r"(h0) : "l"(o2[2 * c]));
            asm("mov.b64 {%0, %1}, %2;" : "=r"(l1), "=r"(h1) : "l"(o2[2 * c + 1]));
            *((float4*)&op[c * 4]) = make_float4(
                __uint_as_float(f2tf(__uint_as_float(l0) * inv)),
                __uint_as_float(f2tf(__uint_as_float(h0) * inv)),
                __uint_as_float(f2tf(__uint_as_float(l1) * inv)),
                __uint_as_float(f2tf(__uint_as_float(h1) * inv)));
        }
    }
}

// ---------------- launch ----------------
extern "C" void kernel_launch(void* const* d_in, const int* in_sizes, int n_in,
                              void* d_out, int out_size)
{
    const float* x      = (const float*)d_in[0];
    const float* qkv_w  = (const float*)d_in[1];
    const float* qkv_b  = (const float*)d_in[2];
    const float* proj_w = (const float*)d_in[3];
    const float* proj_b = (const float*)d_in[4];
    const float* bt     = (const float*)d_in[5];
    const int*   ri     = (const int*)d_in[6];
    float* out = (float*)d_out;

    cudaFuncSetAttribute(gemm_tf32_kernel,
                         cudaFuncAttributeMaxDynamicSharedMemorySize, SMEM_DYN);

    bias_expand_kernel<<<NH, 256>>>(bt, ri);

    {
        int n4 = (M_TOTAL * KDIM) / 4;
        round_tf32_kernel<<<(n4 + 255) / 256, 256>>>(x, n4, 0);
    }
    {
        int n4 = (1152 * KDIM) / 4;
        round_tf32_kernel<<<(n4 + 255) / 256, 256>>>(qkv_w, n4, 1);
    }
    {
        int n4 = (DIMC * KDIM) / 4;
        round_tf32_kernel<<<(n4 + 255) / 256, 256>>>(proj_w, n4, 2);
    }

    dim3 gq(1152 / BN, M_TOTAL / BM);            // 9 x 1568
    gemm_tf32_kernel<<<gq, 256, SMEM_DYN>>>(qkv_b, out, 1152, 0);

    attn_kernel<<<B_WIN * NH, 64>>>();

    dim3 gp(DIMC / BN, M_TOTAL / BM);            // 3 x 1568
    gemm_tf32_kernel<<<gp, 256, SMEM_DYN>>>(proj_b, out, DIMC, 1);
}

// round 12
// speedup vs baseline: 1.2162x; 1.2162x over previous
#include <cuda_runtime.h>
#include <cstdint>

#define B_WIN   4096
#define NTOK    49
#define DIMC    384
#define NH      12
#define HD      32
#define M_TOTAL (B_WIN * NTOK)     // 200704
#define KDIM    384
#define QK_SCALE 0.17677669529663687f

// ---------------- scratch (no cudaMalloc allowed) ----------------
__device__ float g_qkv[(size_t)M_TOTAL * 1152];   // ~925 MB
__device__ float g_att[(size_t)M_TOTAL * DIMC];   // ~308 MB (tf32-rounded by attn)
__device__ float g_xr[(size_t)M_TOTAL * KDIM];    // ~308 MB tf32-rounded x
__device__ float g_wqkv[1152 * KDIM];
__device__ float g_wproj[DIMC * KDIM];
__device__ float g_bias[NH * NTOK * NTOK];

// ---------------- helpers ----------------
__device__ __forceinline__ uint32_t f2tf(float f) {
    uint32_t r;
    asm("cvt.rna.tf32.f32 %0, %1;" : "=r"(r) : "f"(f));
    return r;
}
__device__ __forceinline__ void cpa16(float* smem, const float* g) {
    uint32_t s = (uint32_t)__cvta_generic_to_shared(smem);
    asm volatile("cp.async.cg.shared.global [%0], [%1], 16;\n" :: "r"(s), "l"(g));
}
__device__ __forceinline__ uint64_t fma2(uint64_t a, uint64_t b, uint64_t c) {
    uint64_t d;
    asm("fma.rn.f32x2 %0, %1, %2, %3;" : "=l"(d) : "l"(a), "l"(b), "l"(c));
    return d;
}
__device__ __forceinline__ uint64_t add2(uint64_t a, uint64_t b) {
    uint64_t d;
    asm("add.rn.f32x2 %0, %1, %2;" : "=l"(d) : "l"(a), "l"(b));
    return d;
}

// ---------------- pre-pass: round to tf32 (RNA) ----------------
__global__ void round_tf32_kernel(const float* __restrict__ src, int n4, int mode) {
    float* dst = (mode == 0) ? g_xr : (mode == 1) ? g_wqkv : g_wproj;
    int i = blockIdx.x * blockDim.x + threadIdx.x;
    if (i < n4) {
        float4 v = ((const float4*)src)[i];
        float4 o;
        o.x = __uint_as_float(f2tf(v.x));
        o.y = __uint_as_float(f2tf(v.y));
        o.z = __uint_as_float(f2tf(v.z));
        o.w = __uint_as_float(f2tf(v.w));
        ((float4*)dst)[i] = o;
    }
}

__global__ void bias_expand_kernel(const float* __restrict__ bt, const int* __restrict__ ri) {
    int h = blockIdx.x;
    for (int e = threadIdx.x; e < NTOK * NTOK; e += blockDim.x)
        g_bias[h * NTOK * NTOK + e] = bt[ri[e] * NH + h];
}

// ---------------- tf32 mma.sync GEMM (R7-exact): C = A @ W^T + bias ----------------
// BM=128, BN=64, BK=32, 256 threads (8 warps 4x2), warp tile 32x32.
#define BM  128
#define BN  64
#define BK  32

__device__ __forceinline__ int sw_store(int row, int c4) {
    return row * 32 + ((c4 ^ (row & 7)) << 2);
}
__device__ __forceinline__ uint32_t sw_loadu(const uint32_t* buf, int row, int kc) {
    return buf[row * 32 + ((((kc >> 2)) ^ (row & 7)) << 2) + (kc & 3)];
}

__global__ __launch_bounds__(256) void gemm_tf32_kernel(
    const float* __restrict__ bias, float* __restrict__ Cext, int Nc, int mode)
{
    const float* A = (mode == 0) ? g_xr : g_att;
    const float* W = (mode == 0) ? g_wqkv : g_wproj;
    float*       C = (mode == 0) ? g_qkv : Cext;

    __shared__ float As[2][BM * 32];   // 32KB
    __shared__ float Bs[2][BN * 32];   // 16KB -> 48KB total

    const int tid    = threadIdx.x;
    const int warp   = tid >> 5;
    const int lane   = tid & 31;
    const int g      = lane >> 2;
    const int tg     = lane & 3;
    const int warp_m = warp >> 1;
    const int warp_n = warp & 1;

    const size_t mbase = (size_t)blockIdx.y * BM;
    const size_t nbase = (size_t)blockIdx.x * BN;
    const int KT = KDIM / BK;          // 12

    const int lrow = tid >> 3;
    const int lc4  = tid & 7;

    float acc[2][4][4];
#pragma unroll
    for (int ma = 0; ma < 2; ma++)
#pragma unroll
        for (int na = 0; na < 4; na++)
#pragma unroll
            for (int i = 0; i < 4; i++) acc[ma][na][i] = 0.f;

    auto issue = [&](int t, int buf) {
        const float* Ag = A + (mbase + lrow) * KDIM + t * BK + lc4 * 4;
#pragma unroll
        for (int i = 0; i < 4; i++)
            cpa16(&As[buf][sw_store(lrow + i * 32, lc4)], Ag + (size_t)i * 32 * KDIM);
        const float* Wg = W + (nbase + lrow) * KDIM + t * BK + lc4 * 4;
#pragma unroll
        for (int i = 0; i < 2; i++)
            cpa16(&Bs[buf][sw_store(lrow + i * 32, lc4)], Wg + (size_t)i * 32 * KDIM);
        asm volatile("cp.async.commit_group;\n");
    };

    auto compute = [&](int cur) {
        const uint32_t* Ab = (const uint32_t*)As[cur];
        const uint32_t* Bb = (const uint32_t*)Bs[cur];
#pragma unroll
        for (int ks = 0; ks < 4; ks++) {
            const int kc = ks * 8 + tg;
            uint32_t a[2][4];
#pragma unroll
            for (int ma = 0; ma < 2; ma++) {
                const int r = warp_m * 32 + ma * 16 + g;
                a[ma][0] = sw_loadu(Ab, r,     kc);
                a[ma][1] = sw_loadu(Ab, r + 8, kc);
                a[ma][2] = sw_loadu(Ab, r,     kc + 4);
                a[ma][3] = sw_loadu(Ab, r + 8, kc + 4);
            }
#pragma unroll
            for (int na = 0; na < 4; na++) {
                const int rb = warp_n * 32 + na * 8 + g;
                uint32_t b0 = sw_loadu(Bb, rb, kc);
                uint32_t b1 = sw_loadu(Bb, rb, kc + 4);
#pragma unroll
                for (int ma = 0; ma < 2; ma++) {
                    asm volatile(
                        "mma.sync.aligned.m16n8k8.row.col.f32.tf32.tf32.f32 "
                        "{%0,%1,%2,%3}, {%4,%5,%6,%7}, {%8,%9}, {%0,%1,%2,%3};\n"
                        : "+f"(acc[ma][na][0]), "+f"(acc[ma][na][1]),
                          "+f"(acc[ma][na][2]), "+f"(acc[ma][na][3])
                        : "r"(a[ma][0]), "r"(a[ma][1]), "r"(a[ma][2]), "r"(a[ma][3]),
                          "r"(b0), "r"(b1));
                }
            }
        }
    };

    issue(0, 0);
#pragma unroll 1
    for (int t = 0; t < KT; t++) {
        asm volatile("cp.async.wait_group 0;\n" ::: "memory");
        __syncthreads();
        if (t + 1 < KT) issue(t + 1, (t + 1) & 1);
        compute(t & 1);
    }

    // epilogue
#pragma unroll
    for (int ma = 0; ma < 2; ma++) {
        const size_t r0 = mbase + warp_m * 32 + ma * 16 + g;
#pragma unroll
        for (int na = 0; na < 4; na++) {
            const size_t col = nbase + warp_n * 32 + na * 8 + tg * 2;
            float b0 = __ldg(&bias[col]), b1 = __ldg(&bias[col + 1]);
            *(float2*)&C[r0 * (size_t)Nc + col] =
                make_float2(acc[ma][na][0] + b0, acc[ma][na][1] + b1);
            *(float2*)&C[(r0 + 8) * (size_t)Nc + col] =
                make_float2(acc[ma][na][2] + b0, acc[ma][na][3] + b1);
        }
    }
}

// ---------------- per-(window, head) attention ----------------
// f32x2 math; logits in padded smem (row stride 53, coprime with 32 ->
// conflict-free) to cut regs ~50 and double resident warps.
__global__ __launch_bounds__(64) void attn_kernel()
{
    __shared__ __align__(16) float k_s[NTOK][HD];
    __shared__ __align__(16) float v_s[NTOK][HD];
    __shared__ float s_s[NTOK][53];

    const int bid = blockIdx.x;
    const int b = bid / NH, h = bid % NH;
    const float* base = g_qkv + (size_t)b * NTOK * 1152;
    const int tid = threadIdx.x;

    // prefetch q packed as f32x2 pairs before the K/V barrier
    uint64_t q2[16];
    if (tid < NTOK) {
        const ulonglong2* qp = (const ulonglong2*)(base + (size_t)tid * 1152 + h * HD);
#pragma unroll
        for (int c = 0; c < 8; c++) {
            ulonglong2 t = qp[c];
            q2[2 * c] = t.x; q2[2 * c + 1] = t.y;
        }
    }

    for (int idx = tid; idx < NTOK * 8; idx += 64) {
        int j = idx >> 3, dd = idx & 7;
        const float4* kp = (const float4*)(base + (size_t)j * 1152 + 384 + h * HD);
        *((float4*)&k_s[j][dd * 4]) = kp[dd];
        const float4* vp = (const float4*)(base + (size_t)j * 1152 + 768 + h * HD);
        *((float4*)&v_s[j][dd * 4]) = vp[dd];
    }
    __syncthreads();

    if (tid < NTOK) {
        const float* gb = g_bias + h * (NTOK * NTOK) + tid * NTOK;
        float mx = -1e30f;
#pragma unroll
        for (int j = 0; j < NTOK; j++) {
            const ulonglong2* kr = (const ulonglong2*)k_s[j];
            uint64_t a0 = 0ull, a1 = 0ull, a2 = 0ull, a3 = 0ull;
#pragma unroll
            for (int c = 0; c < 4; c++) {
                ulonglong2 t0 = kr[c];
                ulonglong2 t1 = kr[c + 4];
                a0 = fma2(q2[2 * c],     t0.x, a0);
                a1 = fma2(q2[2 * c + 1], t0.y, a1);
                a2 = fma2(q2[2 * c + 8], t1.x, a2);
                a3 = fma2(q2[2 * c + 9], t1.y, a3);
            }
            a0 = add2(a0, a1);
            a2 = add2(a2, a3);
            a0 = add2(a0, a2);
            uint32_t lo, hi;
            asm("mov.b64 {%0, %1}, %2;" : "=r"(lo), "=r"(hi) : "l"(a0));
            float acc = __uint_as_float(lo) + __uint_as_float(hi);
            float val = acc * QK_SCALE + __ldg(&gb[j]);
            s_s[tid][j] = val;
            mx = fmaxf(mx, val);
        }

        float sum = 0.f;
#pragma unroll
        for (int j = 0; j < NTOK; j++) {
            float e = __expf(s_s[tid][j] - mx);
            s_s[tid][j] = e;
            sum += e;
        }
        float inv = 1.f / sum;

        uint64_t o2[16];
#pragma unroll
        for (int i = 0; i < 16; i++) o2[i] = 0ull;
#pragma unroll
        for (int j = 0; j < NTOK; j++) {
            uint32_t pu = __float_as_uint(s_s[tid][j]);
            uint64_t p2;
            asm("mov.b64 %0, {%1, %2};" : "=l"(p2) : "r"(pu), "r"(pu));
            const ulonglong2* vr = (const ulonglong2*)v_s[j];
#pragma unroll
            for (int c = 0; c < 8; c++) {
                ulonglong2 t = vr[c];
                o2[2 * c]     = fma2(p2, t.x, o2[2 * c]);
                o2[2 * c + 1] = fma2(p2, t.y, o2[2 * c + 1]);
            }
        }

        float* op = g_att + ((size_t)b * NTOK + tid) * DIMC + h * HD;
#pragma unroll
        for (int c = 0; c < 8; c++) {
            uint32_t l0, h0, l1, h1;
            asm("mov.b64 {%0, %1}, %2;" : "=r"(l0), "=r"(h0) : "l"(o2[2 * c]));
            asm("mov.b64 {%0, %1}, %2;" : "=r"(l1), "=r"(h1) : "l"(o2[2 * c + 1]));
            *((float4*)&op[c * 4]) = make_float4(
                __uint_as_float(f2tf(__uint_as_float(l0) * inv)),
                __uint_as_float(f2tf(__uint_as_float(h0) * inv)),
                __uint_as_float(f2tf(__uint_as_float(l1) * inv)),
                __uint_as_float(f2tf(__uint_as_float(h1) * inv)));
        }
    }
}

// ---------------- launch ----------------
extern "C" void kernel_launch(void* const* d_in, const int* in_sizes, int n_in,
                              void* d_out, int out_size)
{
    const float* x      = (const float*)d_in[0];
    const float* qkv_w  = (const float*)d_in[1];
    const float* qkv_b  = (const float*)d_in[2];
    const float* proj_w = (const float*)d_in[3];
    const float* proj_b = (const float*)d_in[4];
    const float* bt     = (const float*)d_in[5];
    const int*   ri     = (const int*)d_in[6];
    float* out = (float*)d_out;

    bias_expand_kernel<<<NH, 256>>>(bt, ri);

    {
        int n4 = (M_TOTAL * KDIM) / 4;
        round_tf32_kernel<<<(n4 + 255) / 256, 256>>>(x, n4, 0);
    }
    {
        int n4 = (1152 * KDIM) / 4;
        round_tf32_kernel<<<(n4 + 255) / 256, 256>>>(qkv_w, n4, 1);
    }
    {
        int n4 = (DIMC * KDIM) / 4;
        round_tf32_kernel<<<(n4 + 255) / 256, 256>>>(proj_w, n4, 2);
    }

    dim3 gq(1152 / BN, M_TOTAL / BM);            // 18 x 1568
    gemm_tf32_kernel<<<gq, 256>>>(qkv_b, out, 1152, 0);

    attn_kernel<<<B_WIN * NH, 64>>>();

    dim3 gp(DIMC / BN, M_TOTAL / BM);            // 6 x 1568
    gemm_tf32_kernel<<<gp, 256>>>(proj_b, out, DIMC, 1);
}

// round 13
// speedup vs baseline: 1.3531x; 1.1126x over previous
#include <cuda_runtime.h>
#include <cstdint>

#define B_WIN   4096
#define NTOK    49
#define DIMC    384
#define NH      12
#define HD      32
#define M_TOTAL (B_WIN * NTOK)     // 200704
#define KDIM    384
#define QK_SCALE 0.17677669529663687f

// ---------------- scratch (no cudaMalloc allowed) ----------------
__device__ float g_qkv[(size_t)M_TOTAL * 1152];   // ~925 MB
__device__ float g_att[(size_t)M_TOTAL * DIMC];   // ~308 MB (tf32-rounded by attn)
__device__ float g_xr[(size_t)M_TOTAL * KDIM];    // ~308 MB tf32-rounded x
__device__ float g_wqkv[1152 * KDIM];
__device__ float g_wproj[DIMC * KDIM];
__device__ float g_bias[NH * NTOK * NTOK];

// ---------------- helpers ----------------
__device__ __forceinline__ uint32_t f2tf(float f) {
    uint32_t r;
    asm("cvt.rna.tf32.f32 %0, %1;" : "=r"(r) : "f"(f));
    return r;
}
__device__ __forceinline__ void cpa16(float* smem, const float* g) {
    uint32_t s = (uint32_t)__cvta_generic_to_shared(smem);
    asm volatile("cp.async.cg.shared.global [%0], [%1], 16;\n" :: "r"(s), "l"(g));
}
__device__ __forceinline__ uint64_t fma2(uint64_t a, uint64_t b, uint64_t c) {
    uint64_t d;
    asm("fma.rn.f32x2 %0, %1, %2, %3;" : "=l"(d) : "l"(a), "l"(b), "l"(c));
    return d;
}
__device__ __forceinline__ uint64_t add2(uint64_t a, uint64_t b) {
    uint64_t d;
    asm("add.rn.f32x2 %0, %1, %2;" : "=l"(d) : "l"(a), "l"(b));
    return d;
}
__device__ __forceinline__ void ldsm4(uint32_t& r0, uint32_t& r1, uint32_t& r2, uint32_t& r3,
                                      uint32_t addr) {
    asm volatile("ldmatrix.sync.aligned.m8n8.x4.shared.b16 {%0,%1,%2,%3}, [%4];"
                 : "=r"(r0), "=r"(r1), "=r"(r2), "=r"(r3) : "r"(addr));
}

// ---------------- pre-pass: round to tf32 (RNA) ----------------
__global__ void round_tf32_kernel(const float* __restrict__ src, int n4, int mode) {
    float* dst = (mode == 0) ? g_xr : (mode == 1) ? g_wqkv : g_wproj;
    int i = blockIdx.x * blockDim.x + threadIdx.x;
    if (i < n4) {
        float4 v = ((const float4*)src)[i];
        float4 o;
        o.x = __uint_as_float(f2tf(v.x));
        o.y = __uint_as_float(f2tf(v.y));
        o.z = __uint_as_float(f2tf(v.z));
        o.w = __uint_as_float(f2tf(v.w));
        ((float4*)dst)[i] = o;
    }
}

__global__ void bias_expand_kernel(const float* __restrict__ bt, const int* __restrict__ ri) {
    int h = blockIdx.x;
    for (int e = threadIdx.x; e < NTOK * NTOK; e += blockDim.x)
        g_bias[h * NTOK * NTOK + e] = bt[ri[e] * NH + h];
}

// ---------------- tf32 mma.sync GEMM: C[M,Nc] = A[M,K] @ W[Nc,K]^T + bias ----------------
// BM=128, BN=64, BK=32, 256 threads (8 warps 4x2), warp tile 32x32 (R7 shape),
// fragments loaded via ldmatrix.x4 (4 LDSM per warp-ks instead of 16 LDS).
#define BM  128
#define BN  64
#define BK  32

__device__ __forceinline__ int sw_store(int row, int c4) {
    return row * 32 + ((c4 ^ (row & 7)) << 2);
}

__global__ __launch_bounds__(256) void gemm_tf32_kernel(
    const float* __restrict__ bias, float* __restrict__ Cext, int Nc, int mode)
{
    const float* A = (mode == 0) ? g_xr : g_att;
    const float* W = (mode == 0) ? g_wqkv : g_wproj;
    float*       C = (mode == 0) ? g_qkv : Cext;

    __shared__ float As[2][BM * 32];   // 32KB
    __shared__ float Bs[2][BN * 32];   // 16KB -> 48KB total

    const int tid    = threadIdx.x;
    const int warp   = tid >> 5;
    const int lane   = tid & 31;
    const int g      = lane >> 2;
    const int tg     = lane & 3;
    const int warp_m = warp >> 1;
    const int warp_n = warp & 1;

    const size_t mbase = (size_t)blockIdx.y * BM;
    const size_t nbase = (size_t)blockIdx.x * BN;
    const int KT = KDIM / BK;          // 12

    const int lrow = tid >> 3;
    const int lc4  = tid & 7;

    // ldmatrix per-thread tile rows:
    // A (per ma): tiles [r..r+7,c4],[r+8..+15,c4],[r..r+7,c4+1],[r+8..+15,c4+1]
    const int arow = warp_m * 32 + ((lane >> 3) & 1) * 8 + (lane & 7);
    const int ahi  = lane >> 4;                       // 0,1 -> chunk offset
    // B: tiles = 4 consecutive 8-row groups -> row = warp_n*32 + lane
    const int brow = warp_n * 32 + lane;

    float acc[2][4][4];
#pragma unroll
    for (int ma = 0; ma < 2; ma++)
#pragma unroll
        for (int na = 0; na < 4; na++)
#pragma unroll
            for (int i = 0; i < 4; i++) acc[ma][na][i] = 0.f;

    auto issue = [&](int t, int buf) {
        const float* Ag = A + (mbase + lrow) * KDIM + t * BK + lc4 * 4;
#pragma unroll
        for (int i = 0; i < 4; i++)
            cpa16(&As[buf][sw_store(lrow + i * 32, lc4)], Ag + (size_t)i * 32 * KDIM);
        const float* Wg = W + (nbase + lrow) * KDIM + t * BK + lc4 * 4;
#pragma unroll
        for (int i = 0; i < 2; i++)
            cpa16(&Bs[buf][sw_store(lrow + i * 32, lc4)], Wg + (size_t)i * 32 * KDIM);
        asm volatile("cp.async.commit_group;\n");
    };

    auto compute = [&](int cur) {
        const uint32_t abase = (uint32_t)__cvta_generic_to_shared(As[cur]);
        const uint32_t bbase = (uint32_t)__cvta_generic_to_shared(Bs[cur]);
#pragma unroll
        for (int ks = 0; ks < 4; ks++) {
            uint32_t a[2][4];
#pragma unroll
            for (int ma = 0; ma < 2; ma++) {
                const int r  = arow + ma * 16;
                const int c4 = ks * 2 + ahi;
                uint32_t addr = abase + (uint32_t)(r * 128 + ((c4 ^ (r & 7)) << 4));
                ldsm4(a[ma][0], a[ma][1], a[ma][2], a[ma][3], addr);
            }
            uint32_t b0[4], b1[4];
            {
                const int c4a = ks * 2;
                uint32_t ad0 = bbase + (uint32_t)(brow * 128 + ((c4a ^ (brow & 7)) << 4));
                uint32_t ad1 = bbase + (uint32_t)(brow * 128 + (((c4a + 1) ^ (brow & 7)) << 4));
                ldsm4(b0[0], b0[1], b0[2], b0[3], ad0);
                ldsm4(b1[0], b1[1], b1[2], b1[3], ad1);
            }
#pragma unroll
            for (int na = 0; na < 4; na++) {
#pragma unroll
                for (int ma = 0; ma < 2; ma++) {
                    asm volatile(
                        "mma.sync.aligned.m16n8k8.row.col.f32.tf32.tf32.f32 "
                        "{%0,%1,%2,%3}, {%4,%5,%6,%7}, {%8,%9}, {%0,%1,%2,%3};\n"
                        : "+f"(acc[ma][na][0]), "+f"(acc[ma][na][1]),
                          "+f"(acc[ma][na][2]), "+f"(acc[ma][na][3])
                        : "r"(a[ma][0]), "r"(a[ma][1]), "r"(a[ma][2]), "r"(a[ma][3]),
                          "r"(b0[na]), "r"(b1[na]));
                }
            }
        }
    };

    issue(0, 0);
#pragma unroll 1
    for (int t = 0; t < KT; t++) {
        asm volatile("cp.async.wait_group 0;\n" ::: "memory");
        __syncthreads();
        if (t + 1 < KT) issue(t + 1, (t + 1) & 1);
        compute(t & 1);
    }

    // epilogue
#pragma unroll
    for (int ma = 0; ma < 2; ma++) {
        const size_t r0 = mbase + warp_m * 32 + ma * 16 + g;
#pragma unroll
        for (int na = 0; na < 4; na++) {
            const size_t col = nbase + warp_n * 32 + na * 8 + tg * 2;
            float b0 = __ldg(&bias[col]), b1 = __ldg(&bias[col + 1]);
            *(float2*)&C[r0 * (size_t)Nc + col] =
                make_float2(acc[ma][na][0] + b0, acc[ma][na][1] + b1);
            *(float2*)&C[(r0 + 8) * (size_t)Nc + col] =
                make_float2(acc[ma][na][2] + b0, acc[ma][na][3] + b1);
        }
    }
}

// ---------------- per-(window, head) attention (R7-exact: registers + f32x2) ----------------
__global__ __launch_bounds__(64) void attn_kernel()
{
    __shared__ __align__(16) float k_s[NTOK][HD];
    __shared__ __align__(16) float v_s[NTOK][HD];

    const int bid = blockIdx.x;
    const int b = bid / NH, h = bid % NH;
    const float* base = g_qkv + (size_t)b * NTOK * 1152;
    const int tid = threadIdx.x;

    uint64_t q2[16];
    if (tid < NTOK) {
        const ulonglong2* qp = (const ulonglong2*)(base + (size_t)tid * 1152 + h * HD);
#pragma unroll
        for (int c = 0; c < 8; c++) {
            ulonglong2 t = qp[c];
            q2[2 * c] = t.x; q2[2 * c + 1] = t.y;
        }
    }

    for (int idx = tid; idx < NTOK * 8; idx += 64) {
        int j = idx >> 3, dd = idx & 7;
        const float4* kp = (const float4*)(base + (size_t)j * 1152 + 384 + h * HD);
        *((float4*)&k_s[j][dd * 4]) = kp[dd];
        const float4* vp = (const float4*)(base + (size_t)j * 1152 + 768 + h * HD);
        *((float4*)&v_s[j][dd * 4]) = vp[dd];
    }
    __syncthreads();

    if (tid < NTOK) {
        const float* gb = g_bias + h * (NTOK * NTOK) + tid * NTOK;
        float s[NTOK];
        float mx = -1e30f;
#pragma unroll
        for (int j = 0; j < NTOK; j++) {
            const ulonglong2* kr = (const ulonglong2*)k_s[j];
            uint64_t a0 = 0ull, a1 = 0ull, a2 = 0ull, a3 = 0ull;
#pragma unroll
            for (int c = 0; c < 4; c++) {
                ulonglong2 t0 = kr[c];
                ulonglong2 t1 = kr[c + 4];
                a0 = fma2(q2[2 * c],     t0.x, a0);
                a1 = fma2(q2[2 * c + 1], t0.y, a1);
                a2 = fma2(q2[2 * c + 8], t1.x, a2);
                a3 = fma2(q2[2 * c + 9], t1.y, a3);
            }
            a0 = add2(a0, a1);
            a2 = add2(a2, a3);
            a0 = add2(a0, a2);
            uint32_t lo, hi;
            asm("mov.b64 {%0, %1}, %2;" : "=r"(lo), "=r"(hi) : "l"(a0));
            float acc = __uint_as_float(lo) + __uint_as_float(hi);
            float val = acc * QK_SCALE + __ldg(&gb[j]);
            s[j] = val;
            mx = fmaxf(mx, val);
        }

        float sum = 0.f;
#pragma unroll
        for (int j = 0; j < NTOK; j++) {
            float e = __expf(s[j] - mx);
            s[j] = e;
            sum += e;
        }
        float inv = 1.f / sum;

        uint64_t o2[16];
#pragma unroll
        for (int i = 0; i < 16; i++) o2[i] = 0ull;
#pragma unroll
        for (int j = 0; j < NTOK; j++) {
            uint32_t pu = __float_as_uint(s[j]);
            uint64_t p2;
            asm("mov.b64 %0, {%1, %2};" : "=l"(p2) : "r"(pu), "r"(pu));
            const ulonglong2* vr = (const ulonglong2*)v_s[j];
#pragma unroll
            for (int c = 0; c < 8; c++) {
                ulonglong2 t = vr[c];
                o2[2 * c]     = fma2(p2, t.x, o2[2 * c]);
                o2[2 * c + 1] = fma2(p2, t.y, o2[2 * c + 1]);
            }
        }

        float* op = g_att + ((size_t)b * NTOK + tid) * DIMC + h * HD;
#pragma unroll
        for (int c = 0; c < 8; c++) {
            uint32_t l0, h0, l1, h1;
            asm("mov.b64 {%0, %1}, %2;" : "=r"(l0), "=r"(h0) : "l"(o2[2 * c]));
            asm("mov.b64 {%0, %1}, %2;" : "=r"(l1), "=r"(h1) : "l"(o2[2 * c + 1]));
            *((float4*)&op[c * 4]) = make_float4(
                __uint_as_float(f2tf(__uint_as_float(l0) * inv)),
                __uint_as_float(f2tf(__uint_as_float(h0) * inv)),
                __uint_as_float(f2tf(__uint_as_float(l1) * inv)),
                __uint_as_float(f2tf(__uint_as_float(h1) * inv)));
        }
    }
}

// ---------------- launch ----------------
extern "C" void kernel_launch(void* const* d_in, const int* in_sizes, int n_in,
                              void* d_out, int out_size)
{
    const float* x      = (const float*)d_in[0];
    const float* qkv_w  = (const float*)d_in[1];
    const float* qkv_b  = (const float*)d_in[2];
    const float* proj_w = (const float*)d_in[3];
    const float* proj_b = (const float*)d_in[4];
    const float* bt     = (const float*)d_in[5];
    const int*   ri     = (const int*)d_in[6];
    float* out = (float*)d_out;

    bias_expand_kernel<<<NH, 256>>>(bt, ri);

    {
        int n4 = (M_TOTAL * KDIM) / 4;
        round_tf32_kernel<<<(n4 + 255) / 256, 256>>>(x, n4, 0);
    }
    {
        int n4 = (1152 * KDIM) / 4;
        round_tf32_kernel<<<(n4 + 255) / 256, 256>>>(qkv_w, n4, 1);
    }
    {
        int n4 = (DIMC * KDIM) / 4;
        round_tf32_kernel<<<(n4 + 255) / 256, 256>>>(proj_w, n4, 2);
    }

    dim3 gq(1152 / BN, M_TOTAL / BM);            // 18 x 1568
    gemm_tf32_kernel<<<gq, 256>>>(qkv_b, out, 1152, 0);

    attn_kernel<<<B_WIN * NH, 64>>>();

    dim3 gp(DIMC / BN, M_TOTAL / BM);            // 6 x 1568
    gemm_tf32_kernel<<<gp, 256>>>(proj_b, out, DIMC, 1);
}